// round 11
// baseline (speedup 1.0000x reference)
#include <cuda_runtime.h>
#include <cstdint>

#define N_NODES 100000
#define N_EDGES 1600000
#define IN_DIM 32
#define OUT_DIM 64
#define N_REL 8
#define K_DIM 256
#define N_KSTEP 36
#define EPS 1e-10f

static constexpr int NPAIRS = N_NODES / 32;      // 3125 exact

// Scratch (alloc-free rule): row-major — edge writes stay 128B-contiguous.
__device__ float g_num[(size_t)N_NODES * K_DIM];
__device__ float g_den[(size_t)N_NODES * N_REL];

__device__ __forceinline__ float to_tf32(float v) {
    uint32_t r;
    asm("cvt.rna.tf32.f32 %0, %1;" : "=r"(r) : "f"(v));
    return __uint_as_float(r);
}
__device__ __forceinline__ uint32_t smem_u32(const void* p) {
    uint32_t a;
    asm("{ .reg .u64 t; cvta.to.shared.u64 t, %1; cvt.u32.u64 %0, t; }"
        : "=r"(a) : "l"(p));
    return a;
}
#define CP_ASYNC16(smem_addr, gptr) \
    asm volatile("cp.async.cg.shared.global [%0], [%1], 16;" \
                 :: "r"(smem_addr), "l"(gptr))
#define CP_COMMIT() asm volatile("cp.async.commit_group;")

// ---------------------------------------------------------------------------
// Kernel 1: edge scatter, 8 lanes per edge (R6 best — unchanged).
// ---------------------------------------------------------------------------
__global__ void scatter_kernel(const int* __restrict__ edge_list,
                               const float* __restrict__ edge_weight,
                               const float* __restrict__ x) {
    const int tid   = threadIdx.x;
    const int gwarp = (blockIdx.x * blockDim.x + tid) >> 5;
    const int lane  = tid & 31;
    const int sub   = lane >> 3;
    const int i8    = lane & 7;

    const int e0 = gwarp * 4;

    int   ev = 0;
    float wv = 0.f;
    if (lane < 12)      ev = edge_list[(size_t)e0 * 3 + lane];
    else if (lane < 16) wv = edge_weight[e0 + (lane - 12)];

    const int   src = __shfl_sync(0xffffffffu, ev, sub * 3 + 0);
    const int   dst = __shfl_sync(0xffffffffu, ev, sub * 3 + 1);
    const int   rel = __shfl_sync(0xffffffffu, ev, sub * 3 + 2);
    const float w   = __shfl_sync(0xffffffffu, wv, 12 + sub);

    const float4 v =
        reinterpret_cast<const float4*>(x + (size_t)src * IN_DIM)[i8];
    float* basep = g_num + (size_t)dst * K_DIM + rel * IN_DIM + i8 * 4;

    asm volatile(
        "red.global.add.v4.f32 [%0], {%1, %2, %3, %4};"
        :: "l"(basep),
           "f"(v.x * w), "f"(v.y * w), "f"(v.z * w), "f"(v.w * w)
        : "memory");

    if (i8 == 0)
        atomicAdd(g_den + (size_t)dst * N_REL + rel, w);
}

// ---------------------------------------------------------------------------
// Kernel 2: tf32 MMA GEMM — m32 per warp (tile pair), shared B-frag reads.
//   B frags k-permuted (slot tt <-> k = s*8 + 2*tt) so A pairs are LDS.64.
//   A left as raw f32 (HMMA.TF32 truncates). 2-stage cp.async ring.
// ---------------------------------------------------------------------------
#define BF_FLOAT2 (N_KSTEP * 8 * 32)
#define BF_BYTES  (BF_FLOAT2 * 8)                 // 73728
#define WROW 36
#define STAGE_FLOATS (32 * WROW)                  // 1152
#define N_STAGE 2
#define WARP_SMEM_FLOATS (N_STAGE * STAGE_FLOATS) // 2304 -> 9216 B/warp
#define WBUF_OFF  (BF_BYTES + OUT_DIM * 4)        // 73984
#define SMEM_TOTAL (WBUF_OFF + 16 * WARP_SMEM_FLOATS * 4)   // 221440

__device__ __forceinline__ void mma_tf32(float c[4], uint32_t a0, uint32_t a1,
                                         uint32_t a2, uint32_t a3,
                                         uint32_t b0, uint32_t b1) {
    asm volatile(
        "mma.sync.aligned.m16n8k8.row.col.f32.tf32.tf32.f32 "
        "{%0,%1,%2,%3}, {%4,%5,%6,%7}, {%8,%9}, {%0,%1,%2,%3};"
        : "+f"(c[0]), "+f"(c[1]), "+f"(c[2]), "+f"(c[3])
        : "r"(a0), "r"(a1), "r"(a2), "r"(a3), "r"(b0), "r"(b1));
}

__global__ __launch_bounds__(512, 1)
void gemm_mma_kernel(const float* __restrict__ x,
                     const float* __restrict__ Wl,
                     const float* __restrict__ bl,
                     const float* __restrict__ Ws,
                     const float* __restrict__ bs,
                     float* __restrict__ out) {
    extern __shared__ char smem[];
    float2* sBf   = reinterpret_cast<float2*>(smem);
    float*  sBias = reinterpret_cast<float*>(smem + BF_BYTES);

    const int tid  = threadIdx.x;
    const int wid  = tid >> 5;
    const int lane = tid & 31;
    const int g    = lane >> 2;
    const int tig  = lane & 3;

    float* wbuf = reinterpret_cast<float*>(smem + WBUF_OFF) +
                  wid * WARP_SMEM_FLOATS;
    const uint32_t wbuf_a = smem_u32(wbuf);

    const int ldrow = lane >> 3;          // 0..3
    const int ldcol = (lane & 7) * 4;     // float offset

    uint32_t dsto[8];
#pragma unroll
    for (int i = 0; i < 8; i++)
        dsto[i] = ((i * 4 + ldrow) * WROW + ldcol) * 4;

    // ---- stage B fragments once (k-permuted: slot tt <-> k = s*8+2*tt) ----
    for (int idx = tid; idx < BF_FLOAT2; idx += 512) {
        const int l  = idx & 31;
        const int j  = (idx >> 5) & 7;
        const int s  = idx >> 8;
        const int gg = l >> 2, tt = l & 3;
        const int n  = j * 8 + gg;
        const int k0 = s * 8 + 2 * tt;
        const int k1 = k0 + 1;
        const float v0 = (k0 < K_DIM) ? Wl[(size_t)k0 * OUT_DIM + n]
                                      : Ws[(size_t)(k0 - K_DIM) * OUT_DIM + n];
        const float v1 = (k1 < K_DIM) ? Wl[(size_t)k1 * OUT_DIM + n]
                                      : Ws[(size_t)(k1 - K_DIM) * OUT_DIM + n];
        sBf[idx] = make_float2(to_tf32(v0), to_tf32(v1));
    }
    if (tid < OUT_DIM) sBias[tid] = bl[tid] + bs[tid];
    __syncthreads();

    const int nwarps = gridDim.x * 16;

    for (int tp = blockIdx.x * 16 + wid; tp < NPAIRS; tp += nwarps) {
        const float* srcA = g_num + (size_t)tp * 32 * K_DIM;
        const float* srcX = x + (size_t)tp * 32 * IN_DIM;

        auto issue = [&](int kb) {
            const uint32_t sb = wbuf_a + (kb & 1) * (STAGE_FLOATS * 4);
            if (kb < 8) {
#pragma unroll
                for (int i = 0; i < 8; i++)
                    CP_ASYNC16(sb + dsto[i],
                               srcA + (size_t)(i * 4 + ldrow) * K_DIM +
                                   kb * 32 + ldcol);
            } else {
#pragma unroll
                for (int i = 0; i < 8; i++)
                    CP_ASYNC16(sb + dsto[i],
                               srcX + (size_t)(i * 4 + ldrow) * IN_DIM + ldcol);
            }
            CP_COMMIT();
        };

        issue(0);
        issue(1);

        // ---- lane-distributed 1/den: lane l holds dv[b] for node tp*32+l ----
        float dv[8];
        {
            const float4* dp = reinterpret_cast<const float4*>(
                g_den + (size_t)(tp * 32 + lane) * N_REL);
            const float4 a = dp[0], b = dp[1];
            dv[0] = __fdividef(1.f, a.x + EPS); dv[1] = __fdividef(1.f, a.y + EPS);
            dv[2] = __fdividef(1.f, a.z + EPS); dv[3] = __fdividef(1.f, a.w + EPS);
            dv[4] = __fdividef(1.f, b.x + EPS); dv[5] = __fdividef(1.f, b.y + EPS);
            dv[6] = __fdividef(1.f, b.z + EPS); dv[7] = __fdividef(1.f, b.w + EPS);
        }

        float acc0[8][4], acc1[8][4];
#pragma unroll
        for (int j = 0; j < 8; j++)
#pragma unroll
            for (int c = 0; c < 4; c++) { acc0[j][c] = 0.f; acc1[j][c] = 0.f; }

#pragma unroll
        for (int kb = 0; kb < 9; kb++) {
            if (kb < 8)
                asm volatile("cp.async.wait_group 1;" ::: "memory");
            else
                asm volatile("cp.async.wait_group 0;" ::: "memory");
            __syncwarp();

            float* buf = wbuf + (kb & 1) * STAGE_FLOATS;

            float d00 = 1.f, d01 = 1.f, d10 = 1.f, d11 = 1.f;
            if (kb < 8) {
                d00 = __shfl_sync(0xffffffffu, dv[kb], g);
                d01 = __shfl_sync(0xffffffffu, dv[kb], g + 8);
                d10 = __shfl_sync(0xffffffffu, dv[kb], g + 16);
                d11 = __shfl_sync(0xffffffffu, dv[kb], g + 24);
            }

#pragma unroll
            for (int ss = 0; ss < 4; ss++) {
                const int fo = ss * 8 + 2 * tig;
                float2 p00 = *reinterpret_cast<const float2*>(buf + g * WROW + fo);
                float2 p01 = *reinterpret_cast<const float2*>(buf + (g + 8) * WROW + fo);
                float2 p10 = *reinterpret_cast<const float2*>(buf + (g + 16) * WROW + fo);
                float2 p11 = *reinterpret_cast<const float2*>(buf + (g + 24) * WROW + fo);
                p00.x *= d00; p00.y *= d00;
                p01.x *= d01; p01.y *= d01;
                p10.x *= d10; p10.y *= d10;
                p11.x *= d11; p11.y *= d11;
                const uint32_t a00 = __float_as_uint(p00.x);
                const uint32_t a02 = __float_as_uint(p00.y);
                const uint32_t a01b = __float_as_uint(p01.x);
                const uint32_t a03 = __float_as_uint(p01.y);
                const uint32_t a10 = __float_as_uint(p10.x);
                const uint32_t a12 = __float_as_uint(p10.y);
                const uint32_t a11 = __float_as_uint(p11.x);
                const uint32_t a13 = __float_as_uint(p11.y);
                const float2* bf = sBf + (kb * 4 + ss) * 256 + lane;
#pragma unroll
                for (int j = 0; j < 8; j++) {
                    const float2 bb = bf[j * 32];
                    const uint32_t b0 = __float_as_uint(bb.x);
                    const uint32_t b1 = __float_as_uint(bb.y);
                    mma_tf32(acc0[j], a00, a01b, a02, a03, b0, b1);
                    mma_tf32(acc1[j], a10, a11, a12, a13, b0, b1);
                }
            }
            __syncwarp();
            if (kb <= 6) issue(kb + 2);
        }

        // ---- epilogue: bias + relu + float2 stores for both tiles ----
        const int r00 = tp * 32 + g;
        const int r01 = r00 + 8;
        const int r10 = r00 + 16;
        const int r11 = r00 + 24;
#pragma unroll
        for (int j = 0; j < 8; j++) {
            const int col = j * 8 + tig * 2;
            const float b0 = sBias[col], b1 = sBias[col + 1];
            float2 v;
            v = make_float2(fmaxf(acc0[j][0] + b0, 0.f), fmaxf(acc0[j][1] + b1, 0.f));
            *reinterpret_cast<float2*>(out + (size_t)r00 * OUT_DIM + col) = v;
            v = make_float2(fmaxf(acc0[j][2] + b0, 0.f), fmaxf(acc0[j][3] + b1, 0.f));
            *reinterpret_cast<float2*>(out + (size_t)r01 * OUT_DIM + col) = v;
            v = make_float2(fmaxf(acc1[j][0] + b0, 0.f), fmaxf(acc1[j][1] + b1, 0.f));
            *reinterpret_cast<float2*>(out + (size_t)r10 * OUT_DIM + col) = v;
            v = make_float2(fmaxf(acc1[j][2] + b0, 0.f), fmaxf(acc1[j][3] + b1, 0.f));
            *reinterpret_cast<float2*>(out + (size_t)r11 * OUT_DIM + col) = v;
        }
    }
}

// ---------------------------------------------------------------------------
// Launch
// ---------------------------------------------------------------------------
extern "C" void kernel_launch(void* const* d_in, const int* in_sizes, int n_in,
                              void* d_out, int out_size) {
    const float* x     = (const float*)d_in[0];
    const int*   edges = (const int*)  d_in[1];
    const float* ew    = (const float*)d_in[2];
    const float* Wl    = (const float*)d_in[3];
    const float* bl    = (const float*)d_in[4];
    const float* Ws    = (const float*)d_in[5];
    const float* bs    = (const float*)d_in[6];
    float*       out   = (float*)d_out;

    void* pnum = nullptr; void* pden = nullptr;
    cudaGetSymbolAddress(&pnum, g_num);
    cudaGetSymbolAddress(&pden, g_den);
    cudaMemsetAsync(pnum, 0, (size_t)N_NODES * K_DIM * sizeof(float), 0);
    cudaMemsetAsync(pden, 0, (size_t)N_NODES * N_REL * sizeof(float), 0);

    scatter_kernel<<<(N_EDGES * 8) / 256, 256>>>(edges, ew, x);

    cudaFuncSetAttribute(gemm_mma_kernel,
                         cudaFuncAttributeMaxDynamicSharedMemorySize,
                         SMEM_TOTAL);
    gemm_mma_kernel<<<148, 512, SMEM_TOTAL>>>(x, Wl, bl, Ws, bs, out);
}

// round 12
// speedup vs baseline: 1.0464x; 1.0464x over previous
#include <cuda_runtime.h>
#include <cstdint>

#define N_NODES 100000
#define N_EDGES 1600000
#define IN_DIM 32
#define OUT_DIM 64
#define N_REL 8
#define K_DIM 256
#define N_KSTEP 36
#define EPS 1e-10f

static constexpr int NROWTILES = N_NODES / 16;   // 6250 exact

// Scratch (alloc-free rule): row-major — edge writes stay 128B-contiguous.
__device__ float g_num[(size_t)N_NODES * K_DIM];
__device__ float g_den[(size_t)N_NODES * N_REL];

__device__ __forceinline__ float to_tf32(float v) {
    uint32_t r;
    asm("cvt.rna.tf32.f32 %0, %1;" : "=r"(r) : "f"(v));
    return __uint_as_float(r);
}
__device__ __forceinline__ uint32_t smem_u32(const void* p) {
    uint32_t a;
    asm("{ .reg .u64 t; cvta.to.shared.u64 t, %1; cvt.u32.u64 %0, t; }"
        : "=r"(a) : "l"(p));
    return a;
}
#define CP_ASYNC16(smem_addr, gptr) \
    asm volatile("cp.async.cg.shared.global [%0], [%1], 16;" \
                 :: "r"(smem_addr), "l"(gptr))
#define CP_COMMIT() asm volatile("cp.async.commit_group;")

// ---------------------------------------------------------------------------
// Kernel 1: edge scatter, 8 lanes per edge (R6 best — unchanged).
// ---------------------------------------------------------------------------
__global__ void scatter_kernel(const int* __restrict__ edge_list,
                               const float* __restrict__ edge_weight,
                               const float* __restrict__ x) {
    const int tid   = threadIdx.x;
    const int gwarp = (blockIdx.x * blockDim.x + tid) >> 5;
    const int lane  = tid & 31;
    const int sub   = lane >> 3;
    const int i8    = lane & 7;

    const int e0 = gwarp * 4;

    int   ev = 0;
    float wv = 0.f;
    if (lane < 12)      ev = edge_list[(size_t)e0 * 3 + lane];
    else if (lane < 16) wv = edge_weight[e0 + (lane - 12)];

    const int   src = __shfl_sync(0xffffffffu, ev, sub * 3 + 0);
    const int   dst = __shfl_sync(0xffffffffu, ev, sub * 3 + 1);
    const int   rel = __shfl_sync(0xffffffffu, ev, sub * 3 + 2);
    const float w   = __shfl_sync(0xffffffffu, wv, 12 + sub);

    const float4 v =
        reinterpret_cast<const float4*>(x + (size_t)src * IN_DIM)[i8];
    float* basep = g_num + (size_t)dst * K_DIM + rel * IN_DIM + i8 * 4;

    asm volatile(
        "red.global.add.v4.f32 [%0], {%1, %2, %3, %4};"
        :: "l"(basep),
           "f"(v.x * w), "f"(v.y * w), "f"(v.z * w), "f"(v.w * w)
        : "memory");

    if (i8 == 0)
        atomicAdd(g_den + (size_t)dst * N_REL + rel, w);
}

// ---------------------------------------------------------------------------
// Kernel 2: tf32 MMA GEMM, cp.async 4-stage per-warp ring (3 in flight).
//   Consumer path identical to R10 (= R7 best).
// ---------------------------------------------------------------------------
#define BF_FLOAT2 (N_KSTEP * 8 * 32)
#define BF_BYTES  (BF_FLOAT2 * 8)                 // 73728
#define WROW 36                                    // floats per staged row
#define WBUF_FLOATS (16 * WROW)                    // 576 per stage
#define N_STAGE 4
#define WARP_SMEM_FLOATS (N_STAGE * WBUF_FLOATS)   // 2304
#define WBUF_OFF  (BF_BYTES + OUT_DIM * 4)         // 73984
#define SMEM_TOTAL (WBUF_OFF + 16 * WARP_SMEM_FLOATS * 4)   // 221440

__device__ __forceinline__ void mma_tf32(float c[4], uint32_t a0, uint32_t a1,
                                         uint32_t a2, uint32_t a3,
                                         uint32_t b0, uint32_t b1) {
    asm volatile(
        "mma.sync.aligned.m16n8k8.row.col.f32.tf32.tf32.f32 "
        "{%0,%1,%2,%3}, {%4,%5,%6,%7}, {%8,%9}, {%0,%1,%2,%3};"
        : "+f"(c[0]), "+f"(c[1]), "+f"(c[2]), "+f"(c[3])
        : "r"(a0), "r"(a1), "r"(a2), "r"(a3), "r"(b0), "r"(b1));
}

__global__ __launch_bounds__(512, 1)
void gemm_mma_kernel(const float* __restrict__ x,
                     const float* __restrict__ Wl,
                     const float* __restrict__ bl,
                     const float* __restrict__ Ws,
                     const float* __restrict__ bs,
                     float* __restrict__ out) {
    extern __shared__ char smem[];
    float2* sBf   = reinterpret_cast<float2*>(smem);
    float*  sBias = reinterpret_cast<float*>(smem + BF_BYTES);

    const int tid  = threadIdx.x;
    const int wid  = tid >> 5;
    const int lane = tid & 31;
    const int g    = lane >> 2;
    const int tig  = lane & 3;

    float* wbuf = reinterpret_cast<float*>(smem + WBUF_OFF) +
                  wid * WARP_SMEM_FLOATS;
    const uint32_t wbuf_a = smem_u32(wbuf);

    const int ldrow = lane >> 3;          // 0..3
    const int ldcol = (lane & 7) * 4;     // float offset

    uint32_t dsto[4];
#pragma unroll
    for (int i = 0; i < 4; i++)
        dsto[i] = ((i * 4 + ldrow) * WROW + ldcol) * 4;

    // ---- stage B fragments once (slot tt <-> k = s*8+tt) ----
    for (int idx = tid; idx < BF_FLOAT2; idx += 512) {
        const int l  = idx & 31;
        const int j  = (idx >> 5) & 7;
        const int s  = idx >> 8;
        const int gg = l >> 2, tt = l & 3;
        const int n  = j * 8 + gg;
        const int k0 = s * 8 + tt;
        const int k1 = k0 + 4;
        const float v0 = (k0 < K_DIM) ? Wl[(size_t)k0 * OUT_DIM + n]
                                      : Ws[(size_t)(k0 - K_DIM) * OUT_DIM + n];
        const float v1 = (k1 < K_DIM) ? Wl[(size_t)k1 * OUT_DIM + n]
                                      : Ws[(size_t)(k1 - K_DIM) * OUT_DIM + n];
        sBf[idx] = make_float2(to_tf32(v0), to_tf32(v1));
    }
    if (tid < OUT_DIM) sBias[tid] = bl[tid] + bs[tid];
    __syncthreads();

    const int nwarps = gridDim.x * 16;

    for (int t = blockIdx.x * 16 + wid; t < NROWTILES; t += nwarps) {
        const float* srcA = g_num + (size_t)t * 16 * K_DIM;
        const float* srcX = x + (size_t)t * 16 * IN_DIM;

        auto issue = [&](int kb) {
            const uint32_t sb = wbuf_a + (kb & 3) * (WBUF_FLOATS * 4);
            if (kb < 8) {
#pragma unroll
                for (int i = 0; i < 4; i++)
                    CP_ASYNC16(sb + dsto[i],
                               srcA + (size_t)(i * 4 + ldrow) * K_DIM +
                                   kb * 32 + ldcol);
            } else {
#pragma unroll
                for (int i = 0; i < 4; i++)
                    CP_ASYNC16(sb + dsto[i],
                               srcX + (size_t)(i * 4 + ldrow) * IN_DIM + ldcol);
            }
            CP_COMMIT();
        };

        issue(0);
        issue(1);
        issue(2);

        // ---- 1/den in registers ----
        float dinv0[8], dinv1[8];
        {
            const int row0 = t * 16 + g;
            const float4* d0 = reinterpret_cast<const float4*>(g_den + (size_t)row0 * N_REL);
            const float4* d1 = reinterpret_cast<const float4*>(g_den + (size_t)(row0 + 8) * N_REL);
            float4 a = d0[0], b = d0[1], c = d1[0], d = d1[1];
            dinv0[0] = __fdividef(1.f, a.x + EPS); dinv0[1] = __fdividef(1.f, a.y + EPS);
            dinv0[2] = __fdividef(1.f, a.z + EPS); dinv0[3] = __fdividef(1.f, a.w + EPS);
            dinv0[4] = __fdividef(1.f, b.x + EPS); dinv0[5] = __fdividef(1.f, b.y + EPS);
            dinv0[6] = __fdividef(1.f, b.z + EPS); dinv0[7] = __fdividef(1.f, b.w + EPS);
            dinv1[0] = __fdividef(1.f, c.x + EPS); dinv1[1] = __fdividef(1.f, c.y + EPS);
            dinv1[2] = __fdividef(1.f, c.z + EPS); dinv1[3] = __fdividef(1.f, c.w + EPS);
            dinv1[4] = __fdividef(1.f, d.x + EPS); dinv1[5] = __fdividef(1.f, d.y + EPS);
            dinv1[6] = __fdividef(1.f, d.z + EPS); dinv1[7] = __fdividef(1.f, d.w + EPS);
        }

        float acc[8][4];
#pragma unroll
        for (int j = 0; j < 8; j++)
#pragma unroll
            for (int c = 0; c < 4; c++) acc[j][c] = 0.f;

#pragma unroll
        for (int kb = 0; kb < 9; kb++) {
            // wait for stage kb: keep up to 2 younger groups in flight
            if (kb < 7)
                asm volatile("cp.async.wait_group 2;" ::: "memory");
            else if (kb == 7)
                asm volatile("cp.async.wait_group 1;" ::: "memory");
            else
                asm volatile("cp.async.wait_group 0;" ::: "memory");
            __syncwarp();

            if (kb <= 5) issue(kb + 3);   // stage (kb-1)&3, consumed last iter

            float* buf = wbuf + (kb & 3) * WBUF_FLOATS;
            const float d0 = (kb < 8) ? dinv0[kb] : 1.f;
            const float d1 = (kb < 8) ? dinv1[kb] : 1.f;

#pragma unroll
            for (int ss = 0; ss < 4; ss++) {
                const int kl = ss * 8 + tig;
                const float f0 = buf[g * WROW + kl];
                const float f2 = buf[g * WROW + kl + 4];
                const float f1 = buf[(g + 8) * WROW + kl];
                const float f3 = buf[(g + 8) * WROW + kl + 4];
                const uint32_t a0 = __float_as_uint(to_tf32(f0 * d0));
                const uint32_t a2 = __float_as_uint(to_tf32(f2 * d0));
                const uint32_t a1 = __float_as_uint(to_tf32(f1 * d1));
                const uint32_t a3 = __float_as_uint(to_tf32(f3 * d1));
                const float2* bf = sBf + (kb * 4 + ss) * 256 + lane;
#pragma unroll
                for (int j = 0; j < 8; j++) {
                    const float2 bb = bf[j * 32];
                    mma_tf32(acc[j], a0, a1, a2, a3,
                             __float_as_uint(bb.x), __float_as_uint(bb.y));
                }
            }
            __syncwarp();   // all lanes done reading before stage reuse
        }

        // ---- epilogue ----
        const int row0 = t * 16 + g;
        const int row1 = row0 + 8;
#pragma unroll
        for (int j = 0; j < 8; j++) {
            const int col = j * 8 + tig * 2;
            const float b0 = sBias[col], b1 = sBias[col + 1];
            float2 v0 = make_float2(fmaxf(acc[j][0] + b0, 0.f),
                                    fmaxf(acc[j][1] + b1, 0.f));
            float2 v1 = make_float2(fmaxf(acc[j][2] + b0, 0.f),
                                    fmaxf(acc[j][3] + b1, 0.f));
            *reinterpret_cast<float2*>(out + (size_t)row0 * OUT_DIM + col) = v0;
            *reinterpret_cast<float2*>(out + (size_t)row1 * OUT_DIM + col) = v1;
        }
    }
}

// ---------------------------------------------------------------------------
// Launch
// ---------------------------------------------------------------------------
extern "C" void kernel_launch(void* const* d_in, const int* in_sizes, int n_in,
                              void* d_out, int out_size) {
    const float* x     = (const float*)d_in[0];
    const int*   edges = (const int*)  d_in[1];
    const float* ew    = (const float*)d_in[2];
    const float* Wl    = (const float*)d_in[3];
    const float* bl    = (const float*)d_in[4];
    const float* Ws    = (const float*)d_in[5];
    const float* bs    = (const float*)d_in[6];
    float*       out   = (float*)d_out;

    void* pnum = nullptr; void* pden = nullptr;
    cudaGetSymbolAddress(&pnum, g_num);
    cudaGetSymbolAddress(&pden, g_den);
    cudaMemsetAsync(pnum, 0, (size_t)N_NODES * K_DIM * sizeof(float), 0);
    cudaMemsetAsync(pden, 0, (size_t)N_NODES * N_REL * sizeof(float), 0);

    scatter_kernel<<<(N_EDGES * 8) / 256, 256>>>(edges, ew, x);

    cudaFuncSetAttribute(gemm_mma_kernel,
                         cudaFuncAttributeMaxDynamicSharedMemorySize,
                         SMEM_TOTAL);
    gemm_mma_kernel<<<148, 512, SMEM_TOTAL>>>(x, Wl, bl, Ws, bs, out);
}

// round 13
// speedup vs baseline: 1.0467x; 1.0003x over previous
#include <cuda_runtime.h>
#include <cstdint>

#define N_NODES 100000
#define N_EDGES 1600000
#define IN_DIM 32
#define OUT_DIM 64
#define N_REL 8
#define K_DIM 256
#define N_KSTEP 36
#define EPS 1e-10f

static constexpr int NROWTILES = N_NODES / 16;   // 6250 exact

// Scratch (alloc-free rule): row-major — edge writes stay 128B-contiguous.
__device__ float g_num[(size_t)N_NODES * K_DIM];
__device__ float g_den[(size_t)N_NODES * N_REL];

__device__ __forceinline__ float to_tf32(float v) {
    uint32_t r;
    asm("cvt.rna.tf32.f32 %0, %1;" : "=r"(r) : "f"(v));
    return __uint_as_float(r);
}
__device__ __forceinline__ uint32_t smem_u32(const void* p) {
    uint32_t a;
    asm("{ .reg .u64 t; cvta.to.shared.u64 t, %1; cvt.u32.u64 %0, t; }"
        : "=r"(a) : "l"(p));
    return a;
}
#define CP_ASYNC16(smem_addr, gptr) \
    asm volatile("cp.async.cg.shared.global [%0], [%1], 16;" \
                 :: "r"(smem_addr), "l"(gptr))
#define CP_COMMIT() asm volatile("cp.async.commit_group;")

// ---------------------------------------------------------------------------
// Kernel 1: edge scatter, 8 lanes per edge.
//   g_num RMWs carry an L2 evict_last hint (fraction 0.7) so accumulated
//   lines stay resident for the GEMM read pass.
// ---------------------------------------------------------------------------
__global__ void scatter_kernel(const int* __restrict__ edge_list,
                               const float* __restrict__ edge_weight,
                               const float* __restrict__ x) {
    const int tid   = threadIdx.x;
    const int gwarp = (blockIdx.x * blockDim.x + tid) >> 5;
    const int lane  = tid & 31;
    const int sub   = lane >> 3;
    const int i8    = lane & 7;

    const int e0 = gwarp * 4;

    int   ev = 0;
    float wv = 0.f;
    if (lane < 12)      ev = edge_list[(size_t)e0 * 3 + lane];
    else if (lane < 16) wv = edge_weight[e0 + (lane - 12)];

    const int   src = __shfl_sync(0xffffffffu, ev, sub * 3 + 0);
    const int   dst = __shfl_sync(0xffffffffu, ev, sub * 3 + 1);
    const int   rel = __shfl_sync(0xffffffffu, ev, sub * 3 + 2);
    const float w   = __shfl_sync(0xffffffffu, wv, 12 + sub);

    uint64_t pol;
    asm volatile("createpolicy.fractional.L2::evict_last.b64 %0, 0.7;"
                 : "=l"(pol));

    const float4 v =
        reinterpret_cast<const float4*>(x + (size_t)src * IN_DIM)[i8];
    float* basep = g_num + (size_t)dst * K_DIM + rel * IN_DIM + i8 * 4;

    asm volatile(
        "red.global.add.L2::cache_hint.v4.f32 [%0], {%1, %2, %3, %4}, %5;"
        :: "l"(basep),
           "f"(v.x * w), "f"(v.y * w), "f"(v.z * w), "f"(v.w * w),
           "l"(pol)
        : "memory");

    if (i8 == 0)
        atomicAdd(g_den + (size_t)dst * N_REL + rel, w);
}

// ---------------------------------------------------------------------------
// Kernel 2: tf32 MMA GEMM, cp.async 4-stage per-warp ring (3 in flight).
//   Identical to R12.
// ---------------------------------------------------------------------------
#define BF_FLOAT2 (N_KSTEP * 8 * 32)
#define BF_BYTES  (BF_FLOAT2 * 8)                 // 73728
#define WROW 36
#define WBUF_FLOATS (16 * WROW)                    // 576 per stage
#define N_STAGE 4
#define WARP_SMEM_FLOATS (N_STAGE * WBUF_FLOATS)   // 2304
#define WBUF_OFF  (BF_BYTES + OUT_DIM * 4)         // 73984
#define SMEM_TOTAL (WBUF_OFF + 16 * WARP_SMEM_FLOATS * 4)   // 221440

__device__ __forceinline__ void mma_tf32(float c[4], uint32_t a0, uint32_t a1,
                                         uint32_t a2, uint32_t a3,
                                         uint32_t b0, uint32_t b1) {
    asm volatile(
        "mma.sync.aligned.m16n8k8.row.col.f32.tf32.tf32.f32 "
        "{%0,%1,%2,%3}, {%4,%5,%6,%7}, {%8,%9}, {%0,%1,%2,%3};"
        : "+f"(c[0]), "+f"(c[1]), "+f"(c[2]), "+f"(c[3])
        : "r"(a0), "r"(a1), "r"(a2), "r"(a3), "r"(b0), "r"(b1));
}

__global__ __launch_bounds__(512, 1)
void gemm_mma_kernel(const float* __restrict__ x,
                     const float* __restrict__ Wl,
                     const float* __restrict__ bl,
                     const float* __restrict__ Ws,
                     const float* __restrict__ bs,
                     float* __restrict__ out) {
    extern __shared__ char smem[];
    float2* sBf   = reinterpret_cast<float2*>(smem);
    float*  sBias = reinterpret_cast<float*>(smem + BF_BYTES);

    const int tid  = threadIdx.x;
    const int wid  = tid >> 5;
    const int lane = tid & 31;
    const int g    = lane >> 2;
    const int tig  = lane & 3;

    float* wbuf = reinterpret_cast<float*>(smem + WBUF_OFF) +
                  wid * WARP_SMEM_FLOATS;
    const uint32_t wbuf_a = smem_u32(wbuf);

    const int ldrow = lane >> 3;
    const int ldcol = (lane & 7) * 4;

    uint32_t dsto[4];
#pragma unroll
    for (int i = 0; i < 4; i++)
        dsto[i] = ((i * 4 + ldrow) * WROW + ldcol) * 4;

    // ---- stage B fragments once (slot tt <-> k = s*8+tt) ----
    for (int idx = tid; idx < BF_FLOAT2; idx += 512) {
        const int l  = idx & 31;
        const int j  = (idx >> 5) & 7;
        const int s  = idx >> 8;
        const int gg = l >> 2, tt = l & 3;
        const int n  = j * 8 + gg;
        const int k0 = s * 8 + tt;
        const int k1 = k0 + 4;
        const float v0 = (k0 < K_DIM) ? Wl[(size_t)k0 * OUT_DIM + n]
                                      : Ws[(size_t)(k0 - K_DIM) * OUT_DIM + n];
        const float v1 = (k1 < K_DIM) ? Wl[(size_t)k1 * OUT_DIM + n]
                                      : Ws[(size_t)(k1 - K_DIM) * OUT_DIM + n];
        sBf[idx] = make_float2(to_tf32(v0), to_tf32(v1));
    }
    if (tid < OUT_DIM) sBias[tid] = bl[tid] + bs[tid];
    __syncthreads();

    const int nwarps = gridDim.x * 16;

    for (int t = blockIdx.x * 16 + wid; t < NROWTILES; t += nwarps) {
        const float* srcA = g_num + (size_t)t * 16 * K_DIM;
        const float* srcX = x + (size_t)t * 16 * IN_DIM;

        auto issue = [&](int kb) {
            const uint32_t sb = wbuf_a + (kb & 3) * (WBUF_FLOATS * 4);
            if (kb < 8) {
#pragma unroll
                for (int i = 0; i < 4; i++)
                    CP_ASYNC16(sb + dsto[i],
                               srcA + (size_t)(i * 4 + ldrow) * K_DIM +
                                   kb * 32 + ldcol);
            } else {
#pragma unroll
                for (int i = 0; i < 4; i++)
                    CP_ASYNC16(sb + dsto[i],
                               srcX + (size_t)(i * 4 + ldrow) * IN_DIM + ldcol);
            }
            CP_COMMIT();
        };

        issue(0);
        issue(1);
        issue(2);

        // ---- 1/den in registers ----
        float dinv0[8], dinv1[8];
        {
            const int row0 = t * 16 + g;
            const float4* d0 = reinterpret_cast<const float4*>(g_den + (size_t)row0 * N_REL);
            const float4* d1 = reinterpret_cast<const float4*>(g_den + (size_t)(row0 + 8) * N_REL);
            float4 a = d0[0], b = d0[1], c = d1[0], d = d1[1];
            dinv0[0] = __fdividef(1.f, a.x + EPS); dinv0[1] = __fdividef(1.f, a.y + EPS);
            dinv0[2] = __fdividef(1.f, a.z + EPS); dinv0[3] = __fdividef(1.f, a.w + EPS);
            dinv0[4] = __fdividef(1.f, b.x + EPS); dinv0[5] = __fdividef(1.f, b.y + EPS);
            dinv0[6] = __fdividef(1.f, b.z + EPS); dinv0[7] = __fdividef(1.f, b.w + EPS);
            dinv1[0] = __fdividef(1.f, c.x + EPS); dinv1[1] = __fdividef(1.f, c.y + EPS);
            dinv1[2] = __fdividef(1.f, c.z + EPS); dinv1[3] = __fdividef(1.f, c.w + EPS);
            dinv1[4] = __fdividef(1.f, d.x + EPS); dinv1[5] = __fdividef(1.f, d.y + EPS);
            dinv1[6] = __fdividef(1.f, d.z + EPS); dinv1[7] = __fdividef(1.f, d.w + EPS);
        }

        float acc[8][4];
#pragma unroll
        for (int j = 0; j < 8; j++)
#pragma unroll
            for (int c = 0; c < 4; c++) acc[j][c] = 0.f;

#pragma unroll
        for (int kb = 0; kb < 9; kb++) {
            if (kb < 7)
                asm volatile("cp.async.wait_group 2;" ::: "memory");
            else if (kb == 7)
                asm volatile("cp.async.wait_group 1;" ::: "memory");
            else
                asm volatile("cp.async.wait_group 0;" ::: "memory");
            __syncwarp();

            if (kb <= 5) issue(kb + 3);

            float* buf = wbuf + (kb & 3) * WBUF_FLOATS;
            const float d0 = (kb < 8) ? dinv0[kb] : 1.f;
            const float d1 = (kb < 8) ? dinv1[kb] : 1.f;

#pragma unroll
            for (int ss = 0; ss < 4; ss++) {
                const int kl = ss * 8 + tig;
                const float f0 = buf[g * WROW + kl];
                const float f2 = buf[g * WROW + kl + 4];
                const float f1 = buf[(g + 8) * WROW + kl];
                const float f3 = buf[(g + 8) * WROW + kl + 4];
                const uint32_t a0 = __float_as_uint(to_tf32(f0 * d0));
                const uint32_t a2 = __float_as_uint(to_tf32(f2 * d0));
                const uint32_t a1 = __float_as_uint(to_tf32(f1 * d1));
                const uint32_t a3 = __float_as_uint(to_tf32(f3 * d1));
                const float2* bf = sBf + (kb * 4 + ss) * 256 + lane;
#pragma unroll
                for (int j = 0; j < 8; j++) {
                    const float2 bb = bf[j * 32];
                    mma_tf32(acc[j], a0, a1, a2, a3,
                             __float_as_uint(bb.x), __float_as_uint(bb.y));
                }
            }
            __syncwarp();
        }

        // ---- epilogue ----
        const int row0 = t * 16 + g;
        const int row1 = row0 + 8;
#pragma unroll
        for (int j = 0; j < 8; j++) {
            const int col = j * 8 + tig * 2;
            const float b0 = sBias[col], b1 = sBias[col + 1];
            float2 v0 = make_float2(fmaxf(acc[j][0] + b0, 0.f),
                                    fmaxf(acc[j][1] + b1, 0.f));
            float2 v1 = make_float2(fmaxf(acc[j][2] + b0, 0.f),
                                    fmaxf(acc[j][3] + b1, 0.f));
            *reinterpret_cast<float2*>(out + (size_t)row0 * OUT_DIM + col) = v0;
            *reinterpret_cast<float2*>(out + (size_t)row1 * OUT_DIM + col) = v1;
        }
    }
}

// ---------------------------------------------------------------------------
// Launch
// ---------------------------------------------------------------------------
extern "C" void kernel_launch(void* const* d_in, const int* in_sizes, int n_in,
                              void* d_out, int out_size) {
    const float* x     = (const float*)d_in[0];
    const int*   edges = (const int*)  d_in[1];
    const float* ew    = (const float*)d_in[2];
    const float* Wl    = (const float*)d_in[3];
    const float* bl    = (const float*)d_in[4];
    const float* Ws    = (const float*)d_in[5];
    const float* bs    = (const float*)d_in[6];
    float*       out   = (float*)d_out;

    void* pnum = nullptr; void* pden = nullptr;
    cudaGetSymbolAddress(&pnum, g_num);
    cudaGetSymbolAddress(&pden, g_den);
    cudaMemsetAsync(pnum, 0, (size_t)N_NODES * K_DIM * sizeof(float), 0);
    cudaMemsetAsync(pden, 0, (size_t)N_NODES * N_REL * sizeof(float), 0);

    scatter_kernel<<<(N_EDGES * 8) / 256, 256>>>(edges, ew, x);

    cudaFuncSetAttribute(gemm_mma_kernel,
                         cudaFuncAttributeMaxDynamicSharedMemorySize,
                         SMEM_TOTAL);
    gemm_mma_kernel<<<148, 512, SMEM_TOTAL>>>(x, Wl, bl, Ws, bs, out);
}

// round 14
// speedup vs baseline: 1.0806x; 1.0324x over previous
#include <cuda_runtime.h>
#include <cstdint>

#define N_NODES 100000
#define N_EDGES 1600000
#define IN_DIM 32
#define OUT_DIM 64
#define N_REL 8
#define K_DIM 256
#define N_KSTEP 36
#define EPS 1e-10f

static constexpr int NROWTILES = N_NODES / 16;   // 6250 exact

// Scratch (alloc-free rule). Zero-initialized at module load; the GEMM
// re-zeroes every region after consuming it, so each graph replay starts
// from zeroed scratch without any memset pass.
__device__ float g_num[(size_t)N_NODES * K_DIM];
__device__ float g_den[(size_t)N_NODES * N_REL];

__device__ __forceinline__ float to_tf32(float v) {
    uint32_t r;
    asm("cvt.rna.tf32.f32 %0, %1;" : "=r"(r) : "f"(v));
    return __uint_as_float(r);
}
__device__ __forceinline__ uint32_t smem_u32(const void* p) {
    uint32_t a;
    asm("{ .reg .u64 t; cvta.to.shared.u64 t, %1; cvt.u32.u64 %0, t; }"
        : "=r"(a) : "l"(p));
    return a;
}
#define CP_ASYNC16(smem_addr, gptr) \
    asm volatile("cp.async.cg.shared.global [%0], [%1], 16;" \
                 :: "r"(smem_addr), "l"(gptr))
#define CP_COMMIT() asm volatile("cp.async.commit_group;")

// ---------------------------------------------------------------------------
// Kernel 1: edge scatter, 8 lanes per edge (R6 best — unchanged).
// ---------------------------------------------------------------------------
__global__ void scatter_kernel(const int* __restrict__ edge_list,
                               const float* __restrict__ edge_weight,
                               const float* __restrict__ x) {
    const int tid   = threadIdx.x;
    const int gwarp = (blockIdx.x * blockDim.x + tid) >> 5;
    const int lane  = tid & 31;
    const int sub   = lane >> 3;
    const int i8    = lane & 7;

    const int e0 = gwarp * 4;

    int   ev = 0;
    float wv = 0.f;
    if (lane < 12)      ev = edge_list[(size_t)e0 * 3 + lane];
    else if (lane < 16) wv = edge_weight[e0 + (lane - 12)];

    const int   src = __shfl_sync(0xffffffffu, ev, sub * 3 + 0);
    const int   dst = __shfl_sync(0xffffffffu, ev, sub * 3 + 1);
    const int   rel = __shfl_sync(0xffffffffu, ev, sub * 3 + 2);
    const float w   = __shfl_sync(0xffffffffu, wv, 12 + sub);

    const float4 v =
        reinterpret_cast<const float4*>(x + (size_t)src * IN_DIM)[i8];
    float* basep = g_num + (size_t)dst * K_DIM + rel * IN_DIM + i8 * 4;

    asm volatile(
        "red.global.add.v4.f32 [%0], {%1, %2, %3, %4};"
        :: "l"(basep),
           "f"(v.x * w), "f"(v.y * w), "f"(v.z * w), "f"(v.w * w)
        : "memory");

    if (i8 == 0)
        atomicAdd(g_den + (size_t)dst * N_REL + rel, w);
}

// ---------------------------------------------------------------------------
// Kernel 2: tf32 MMA GEMM, cp.async 4-stage ring; self-cleaning scratch
//   (zeroes g_num/g_den regions after consuming them).
// ---------------------------------------------------------------------------
#define BF_FLOAT2 (N_KSTEP * 8 * 32)
#define BF_BYTES  (BF_FLOAT2 * 8)                 // 73728
#define WROW 36
#define WBUF_FLOATS (16 * WROW)                    // 576 per stage
#define N_STAGE 4
#define WARP_SMEM_FLOATS (N_STAGE * WBUF_FLOATS)   // 2304
#define WBUF_OFF  (BF_BYTES + OUT_DIM * 4)         // 73984
#define SMEM_TOTAL (WBUF_OFF + 16 * WARP_SMEM_FLOATS * 4)   // 221440

__device__ __forceinline__ void mma_tf32(float c[4], uint32_t a0, uint32_t a1,
                                         uint32_t a2, uint32_t a3,
                                         uint32_t b0, uint32_t b1) {
    asm volatile(
        "mma.sync.aligned.m16n8k8.row.col.f32.tf32.tf32.f32 "
        "{%0,%1,%2,%3}, {%4,%5,%6,%7}, {%8,%9}, {%0,%1,%2,%3};"
        : "+f"(c[0]), "+f"(c[1]), "+f"(c[2]), "+f"(c[3])
        : "r"(a0), "r"(a1), "r"(a2), "r"(a3), "r"(b0), "r"(b1));
}

__global__ __launch_bounds__(512, 1)
void gemm_mma_kernel(const float* __restrict__ x,
                     const float* __restrict__ Wl,
                     const float* __restrict__ bl,
                     const float* __restrict__ Ws,
                     const float* __restrict__ bs,
                     float* __restrict__ out) {
    extern __shared__ char smem[];
    float2* sBf   = reinterpret_cast<float2*>(smem);
    float*  sBias = reinterpret_cast<float*>(smem + BF_BYTES);

    const int tid  = threadIdx.x;
    const int wid  = tid >> 5;
    const int lane = tid & 31;
    const int g    = lane >> 2;
    const int tig  = lane & 3;

    float* wbuf = reinterpret_cast<float*>(smem + WBUF_OFF) +
                  wid * WARP_SMEM_FLOATS;
    const uint32_t wbuf_a = smem_u32(wbuf);

    const int ldrow = lane >> 3;
    const int ldcol = (lane & 7) * 4;

    uint32_t dsto[4];
#pragma unroll
    for (int i = 0; i < 4; i++)
        dsto[i] = ((i * 4 + ldrow) * WROW + ldcol) * 4;

    // ---- stage B fragments once (slot tt <-> k = s*8+tt) ----
    for (int idx = tid; idx < BF_FLOAT2; idx += 512) {
        const int l  = idx & 31;
        const int j  = (idx >> 5) & 7;
        const int s  = idx >> 8;
        const int gg = l >> 2, tt = l & 3;
        const int n  = j * 8 + gg;
        const int k0 = s * 8 + tt;
        const int k1 = k0 + 4;
        const float v0 = (k0 < K_DIM) ? Wl[(size_t)k0 * OUT_DIM + n]
                                      : Ws[(size_t)(k0 - K_DIM) * OUT_DIM + n];
        const float v1 = (k1 < K_DIM) ? Wl[(size_t)k1 * OUT_DIM + n]
                                      : Ws[(size_t)(k1 - K_DIM) * OUT_DIM + n];
        sBf[idx] = make_float2(to_tf32(v0), to_tf32(v1));
    }
    if (tid < OUT_DIM) sBias[tid] = bl[tid] + bs[tid];
    __syncthreads();

    const float4 zero4 = make_float4(0.f, 0.f, 0.f, 0.f);
    const int nwarps = gridDim.x * 16;

    for (int t = blockIdx.x * 16 + wid; t < NROWTILES; t += nwarps) {
        const float* srcA = g_num + (size_t)t * 16 * K_DIM;
        const float* srcX = x + (size_t)t * 16 * IN_DIM;

        auto issue = [&](int kb) {
            const uint32_t sb = wbuf_a + (kb & 3) * (WBUF_FLOATS * 4);
            if (kb < 8) {
#pragma unroll
                for (int i = 0; i < 4; i++)
                    CP_ASYNC16(sb + dsto[i],
                               srcA + (size_t)(i * 4 + ldrow) * K_DIM +
                                   kb * 32 + ldcol);
            } else {
#pragma unroll
                for (int i = 0; i < 4; i++)
                    CP_ASYNC16(sb + dsto[i],
                               srcX + (size_t)(i * 4 + ldrow) * IN_DIM + ldcol);
            }
            CP_COMMIT();
        };

        issue(0);
        issue(1);
        issue(2);

        // ---- 1/den in registers; then zero this tile's g_den region ----
        float dinv0[8], dinv1[8];
        {
            const int row0 = t * 16 + g;
            const float4* d0 = reinterpret_cast<const float4*>(g_den + (size_t)row0 * N_REL);
            const float4* d1 = reinterpret_cast<const float4*>(g_den + (size_t)(row0 + 8) * N_REL);
            float4 a = d0[0], b = d0[1], c = d1[0], d = d1[1];
            dinv0[0] = __fdividef(1.f, a.x + EPS); dinv0[1] = __fdividef(1.f, a.y + EPS);
            dinv0[2] = __fdividef(1.f, a.z + EPS); dinv0[3] = __fdividef(1.f, a.w + EPS);
            dinv0[4] = __fdividef(1.f, b.x + EPS); dinv0[5] = __fdividef(1.f, b.y + EPS);
            dinv0[6] = __fdividef(1.f, b.z + EPS); dinv0[7] = __fdividef(1.f, b.w + EPS);
            dinv1[0] = __fdividef(1.f, c.x + EPS); dinv1[1] = __fdividef(1.f, c.y + EPS);
            dinv1[2] = __fdividef(1.f, c.z + EPS); dinv1[3] = __fdividef(1.f, c.w + EPS);
            dinv1[4] = __fdividef(1.f, d.x + EPS); dinv1[5] = __fdividef(1.f, d.y + EPS);
            dinv1[6] = __fdividef(1.f, d.z + EPS); dinv1[7] = __fdividef(1.f, d.w + EPS);
        }
        __syncwarp();   // all lanes' den reads complete before zeroing
        // 16 rows * 8 floats = 128 floats = 32 float4 -> one per lane
        reinterpret_cast<float4*>(g_den + (size_t)t * 16 * N_REL)[lane] = zero4;

        float acc[8][4];
#pragma unroll
        for (int j = 0; j < 8; j++)
#pragma unroll
            for (int c = 0; c < 4; c++) acc[j][c] = 0.f;

#pragma unroll
        for (int kb = 0; kb < 9; kb++) {
            if (kb < 7)
                asm volatile("cp.async.wait_group 2;" ::: "memory");
            else if (kb == 7)
                asm volatile("cp.async.wait_group 1;" ::: "memory");
            else
                asm volatile("cp.async.wait_group 0;" ::: "memory");
            __syncwarp();

            // stage kb's global data is now in SMEM: zero it for next replay
            if (kb < 8) {
#pragma unroll
                for (int i = 0; i < 4; i++)
                    *reinterpret_cast<float4*>(const_cast<float*>(
                        srcA + (size_t)(i * 4 + ldrow) * K_DIM +
                        kb * 32 + ldcol)) = zero4;
            }

            if (kb <= 5) issue(kb + 3);

            float* buf = wbuf + (kb & 3) * WBUF_FLOATS;
            const float d0 = (kb < 8) ? dinv0[kb] : 1.f;
            const float d1 = (kb < 8) ? dinv1[kb] : 1.f;

#pragma unroll
            for (int ss = 0; ss < 4; ss++) {
                const int kl = ss * 8 + tig;
                const float f0 = buf[g * WROW + kl];
                const float f2 = buf[g * WROW + kl + 4];
                const float f1 = buf[(g + 8) * WROW + kl];
                const float f3 = buf[(g + 8) * WROW + kl + 4];
                const uint32_t a0 = __float_as_uint(to_tf32(f0 * d0));
                const uint32_t a2 = __float_as_uint(to_tf32(f2 * d0));
                const uint32_t a1 = __float_as_uint(to_tf32(f1 * d1));
                const uint32_t a3 = __float_as_uint(to_tf32(f3 * d1));
                const float2* bf = sBf + (kb * 4 + ss) * 256 + lane;
#pragma unroll
                for (int j = 0; j < 8; j++) {
                    const float2 bb = bf[j * 32];
                    mma_tf32(acc[j], a0, a1, a2, a3,
                             __float_as_uint(bb.x), __float_as_uint(bb.y));
                }
            }
            __syncwarp();
        }

        // ---- epilogue ----
        const int row0 = t * 16 + g;
        const int row1 = row0 + 8;
#pragma unroll
        for (int j = 0; j < 8; j++) {
            const int col = j * 8 + tig * 2;
            const float b0 = sBias[col], b1 = sBias[col + 1];
            float2 v0 = make_float2(fmaxf(acc[j][0] + b0, 0.f),
                                    fmaxf(acc[j][1] + b1, 0.f));
            float2 v1 = make_float2(fmaxf(acc[j][2] + b0, 0.f),
                                    fmaxf(acc[j][3] + b1, 0.f));
            *reinterpret_cast<float2*>(out + (size_t)row0 * OUT_DIM + col) = v0;
            *reinterpret_cast<float2*>(out + (size_t)row1 * OUT_DIM + col) = v1;
        }
    }
}

// ---------------------------------------------------------------------------
// Launch — two kernels only; no memsets (scratch self-cleans each replay).
// ---------------------------------------------------------------------------
extern "C" void kernel_launch(void* const* d_in, const int* in_sizes, int n_in,
                              void* d_out, int out_size) {
    const float* x     = (const float*)d_in[0];
    const int*   edges = (const int*)  d_in[1];
    const float* ew    = (const float*)d_in[2];
    const float* Wl    = (const float*)d_in[3];
    const float* bl    = (const float*)d_in[4];
    const float* Ws    = (const float*)d_in[5];
    const float* bs    = (const float*)d_in[6];
    float*       out   = (float*)d_out;

    scatter_kernel<<<(N_EDGES * 8) / 256, 256>>>(edges, ew, x);

    cudaFuncSetAttribute(gemm_mma_kernel,
                         cudaFuncAttributeMaxDynamicSharedMemorySize,
                         SMEM_TOTAL);
    gemm_mma_kernel<<<148, 512, SMEM_TOTAL>>>(x, Wl, bl, Ws, bs, out);
}

// round 15
// speedup vs baseline: 1.0928x; 1.0113x over previous
#include <cuda_runtime.h>
#include <cstdint>

#define N_NODES 100000
#define N_EDGES 1600000
#define IN_DIM 32
#define OUT_DIM 64
#define N_REL 8
#define K_DIM 256
#define N_KSTEP 36
#define EPS 1e-10f

static constexpr int NROWTILES = N_NODES / 16;   // 6250 exact

// Scratch (alloc-free rule). Zero at module load; GEMM re-zeroes each region
// after consuming it, so every graph replay starts from zeroed scratch.
__device__ float g_num[(size_t)N_NODES * K_DIM];
__device__ float g_den[(size_t)N_NODES * N_REL];

__device__ __forceinline__ float to_tf32(float v) {
    uint32_t r;
    asm("cvt.rna.tf32.f32 %0, %1;" : "=r"(r) : "f"(v));
    return __uint_as_float(r);
}
__device__ __forceinline__ uint32_t smem_u32(const void* p) {
    uint32_t a;
    asm("{ .reg .u64 t; cvta.to.shared.u64 t, %1; cvt.u32.u64 %0, t; }"
        : "=r"(a) : "l"(p));
    return a;
}
#define CP_ASYNC16(smem_addr, gptr) \
    asm volatile("cp.async.cg.shared.global [%0], [%1], 16;" \
                 :: "r"(smem_addr), "l"(gptr))
#define CP_COMMIT() asm volatile("cp.async.commit_group;")
// streaming zero store (evict-first): not re-read until next replay's scatter
#define STG128_CS_ZERO(gptr) \
    asm volatile("st.global.cs.v4.f32 [%0], {%1, %1, %1, %1};" \
                 :: "l"(gptr), "f"(0.0f) : "memory")

// ---------------------------------------------------------------------------
// Kernel 1: edge scatter, 8 lanes per edge (R6 best — unchanged).
// ---------------------------------------------------------------------------
__global__ void scatter_kernel(const int* __restrict__ edge_list,
                               const float* __restrict__ edge_weight,
                               const float* __restrict__ x) {
    const int tid   = threadIdx.x;
    const int gwarp = (blockIdx.x * blockDim.x + tid) >> 5;
    const int lane  = tid & 31;
    const int sub   = lane >> 3;
    const int i8    = lane & 7;

    const int e0 = gwarp * 4;

    int   ev = 0;
    float wv = 0.f;
    if (lane < 12)      ev = edge_list[(size_t)e0 * 3 + lane];
    else if (lane < 16) wv = edge_weight[e0 + (lane - 12)];

    const int   src = __shfl_sync(0xffffffffu, ev, sub * 3 + 0);
    const int   dst = __shfl_sync(0xffffffffu, ev, sub * 3 + 1);
    const int   rel = __shfl_sync(0xffffffffu, ev, sub * 3 + 2);
    const float w   = __shfl_sync(0xffffffffu, wv, 12 + sub);

    const float4 v =
        reinterpret_cast<const float4*>(x + (size_t)src * IN_DIM)[i8];
    float* basep = g_num + (size_t)dst * K_DIM + rel * IN_DIM + i8 * 4;

    asm volatile(
        "red.global.add.v4.f32 [%0], {%1, %2, %3, %4};"
        :: "l"(basep),
           "f"(v.x * w), "f"(v.y * w), "f"(v.z * w), "f"(v.w * w)
        : "memory");

    if (i8 == 0)
        atomicAdd(g_den + (size_t)dst * N_REL + rel, w);
}

// ---------------------------------------------------------------------------
// Kernel 2: tf32 MMA GEMM, cp.async 4-stage ring; self-cleaning scratch.
//   Zero-stores hoisted to a per-tile flush AFTER the k-loop (off the MMA
//   critical path), streamed with .cs.
// ---------------------------------------------------------------------------
#define BF_FLOAT2 (N_KSTEP * 8 * 32)
#define BF_BYTES  (BF_FLOAT2 * 8)                 // 73728
#define WROW 36
#define WBUF_FLOATS (16 * WROW)                    // 576 per stage
#define N_STAGE 4
#define WARP_SMEM_FLOATS (N_STAGE * WBUF_FLOATS)   // 2304
#define WBUF_OFF  (BF_BYTES + OUT_DIM * 4)         // 73984
#define SMEM_TOTAL (WBUF_OFF + 16 * WARP_SMEM_FLOATS * 4)   // 221440

__device__ __forceinline__ void mma_tf32(float c[4], uint32_t a0, uint32_t a1,
                                         uint32_t a2, uint32_t a3,
                                         uint32_t b0, uint32_t b1) {
    asm volatile(
        "mma.sync.aligned.m16n8k8.row.col.f32.tf32.tf32.f32 "
        "{%0,%1,%2,%3}, {%4,%5,%6,%7}, {%8,%9}, {%0,%1,%2,%3};"
        : "+f"(c[0]), "+f"(c[1]), "+f"(c[2]), "+f"(c[3])
        : "r"(a0), "r"(a1), "r"(a2), "r"(a3), "r"(b0), "r"(b1));
}

__global__ __launch_bounds__(512, 1)
void gemm_mma_kernel(const float* __restrict__ x,
                     const float* __restrict__ Wl,
                     const float* __restrict__ bl,
                     const float* __restrict__ Ws,
                     const float* __restrict__ bs,
                     float* __restrict__ out) {
    extern __shared__ char smem[];
    float2* sBf   = reinterpret_cast<float2*>(smem);
    float*  sBias = reinterpret_cast<float*>(smem + BF_BYTES);

    const int tid  = threadIdx.x;
    const int wid  = tid >> 5;
    const int lane = tid & 31;
    const int g    = lane >> 2;
    const int tig  = lane & 3;

    float* wbuf = reinterpret_cast<float*>(smem + WBUF_OFF) +
                  wid * WARP_SMEM_FLOATS;
    const uint32_t wbuf_a = smem_u32(wbuf);

    const int ldrow = lane >> 3;
    const int ldcol = (lane & 7) * 4;

    uint32_t dsto[4];
#pragma unroll
    for (int i = 0; i < 4; i++)
        dsto[i] = ((i * 4 + ldrow) * WROW + ldcol) * 4;

    // ---- stage B fragments once (slot tt <-> k = s*8+tt) ----
    for (int idx = tid; idx < BF_FLOAT2; idx += 512) {
        const int l  = idx & 31;
        const int j  = (idx >> 5) & 7;
        const int s  = idx >> 8;
        const int gg = l >> 2, tt = l & 3;
        const int n  = j * 8 + gg;
        const int k0 = s * 8 + tt;
        const int k1 = k0 + 4;
        const float v0 = (k0 < K_DIM) ? Wl[(size_t)k0 * OUT_DIM + n]
                                      : Ws[(size_t)(k0 - K_DIM) * OUT_DIM + n];
        const float v1 = (k1 < K_DIM) ? Wl[(size_t)k1 * OUT_DIM + n]
                                      : Ws[(size_t)(k1 - K_DIM) * OUT_DIM + n];
        sBf[idx] = make_float2(to_tf32(v0), to_tf32(v1));
    }
    if (tid < OUT_DIM) sBias[tid] = bl[tid] + bs[tid];
    __syncthreads();

    const float4 zero4 = make_float4(0.f, 0.f, 0.f, 0.f);
    const int nwarps = gridDim.x * 16;

    for (int t = blockIdx.x * 16 + wid; t < NROWTILES; t += nwarps) {
        const float* srcA = g_num + (size_t)t * 16 * K_DIM;
        const float* srcX = x + (size_t)t * 16 * IN_DIM;

        auto issue = [&](int kb) {
            const uint32_t sb = wbuf_a + (kb & 3) * (WBUF_FLOATS * 4);
            if (kb < 8) {
#pragma unroll
                for (int i = 0; i < 4; i++)
                    CP_ASYNC16(sb + dsto[i],
                               srcA + (size_t)(i * 4 + ldrow) * K_DIM +
                                   kb * 32 + ldcol);
            } else {
#pragma unroll
                for (int i = 0; i < 4; i++)
                    CP_ASYNC16(sb + dsto[i],
                               srcX + (size_t)(i * 4 + ldrow) * IN_DIM + ldcol);
            }
            CP_COMMIT();
        };

        issue(0);
        issue(1);
        issue(2);

        // ---- 1/den in registers; zero this tile's g_den region ----
        float dinv0[8], dinv1[8];
        {
            const int row0 = t * 16 + g;
            const float4* d0 = reinterpret_cast<const float4*>(g_den + (size_t)row0 * N_REL);
            const float4* d1 = reinterpret_cast<const float4*>(g_den + (size_t)(row0 + 8) * N_REL);
            float4 a = d0[0], b = d0[1], c = d1[0], d = d1[1];
            dinv0[0] = __fdividef(1.f, a.x + EPS); dinv0[1] = __fdividef(1.f, a.y + EPS);
            dinv0[2] = __fdividef(1.f, a.z + EPS); dinv0[3] = __fdividef(1.f, a.w + EPS);
            dinv0[4] = __fdividef(1.f, b.x + EPS); dinv0[5] = __fdividef(1.f, b.y + EPS);
            dinv0[6] = __fdividef(1.f, b.z + EPS); dinv0[7] = __fdividef(1.f, b.w + EPS);
            dinv1[0] = __fdividef(1.f, c.x + EPS); dinv1[1] = __fdividef(1.f, c.y + EPS);
            dinv1[2] = __fdividef(1.f, c.z + EPS); dinv1[3] = __fdividef(1.f, c.w + EPS);
            dinv1[4] = __fdividef(1.f, d.x + EPS); dinv1[5] = __fdividef(1.f, d.y + EPS);
            dinv1[6] = __fdividef(1.f, d.z + EPS); dinv1[7] = __fdividef(1.f, d.w + EPS);
        }
        __syncwarp();   // all lanes' den reads complete before zeroing
        reinterpret_cast<float4*>(g_den + (size_t)t * 16 * N_REL)[lane] = zero4;

        float acc[8][4];
#pragma unroll
        for (int j = 0; j < 8; j++)
#pragma unroll
            for (int c = 0; c < 4; c++) acc[j][c] = 0.f;

#pragma unroll
        for (int kb = 0; kb < 9; kb++) {
            if (kb < 7)
                asm volatile("cp.async.wait_group 2;" ::: "memory");
            else if (kb == 7)
                asm volatile("cp.async.wait_group 1;" ::: "memory");
            else
                asm volatile("cp.async.wait_group 0;" ::: "memory");
            __syncwarp();

            if (kb <= 5) issue(kb + 3);

            float* buf = wbuf + (kb & 3) * WBUF_FLOATS;
            const float d0 = (kb < 8) ? dinv0[kb] : 1.f;
            const float d1 = (kb < 8) ? dinv1[kb] : 1.f;

#pragma unroll
            for (int ss = 0; ss < 4; ss++) {
                const int kl = ss * 8 + tig;
                const float f0 = buf[g * WROW + kl];
                const float f2 = buf[g * WROW + kl + 4];
                const float f1 = buf[(g + 8) * WROW + kl];
                const float f3 = buf[(g + 8) * WROW + kl + 4];
                const uint32_t a0 = __float_as_uint(to_tf32(f0 * d0));
                const uint32_t a2 = __float_as_uint(to_tf32(f2 * d0));
                const uint32_t a1 = __float_as_uint(to_tf32(f1 * d1));
                const uint32_t a3 = __float_as_uint(to_tf32(f3 * d1));
                const float2* bf = sBf + (kb * 4 + ss) * 256 + lane;
#pragma unroll
                for (int j = 0; j < 8; j++) {
                    const float2 bb = bf[j * 32];
                    mma_tf32(acc[j], a0, a1, a2, a3,
                             __float_as_uint(bb.x), __float_as_uint(bb.y));
                }
            }
            __syncwarp();
        }

        // ---- zero-flush: all 8 k-blocks of this tile's g_num, streamed ----
        // (every stage consumed above; batched stores have full MLP and
        //  overlap the epilogue + next tile's prologue)
#pragma unroll
        for (int kb = 0; kb < 8; kb++)
#pragma unroll
            for (int i = 0; i < 4; i++)
                STG128_CS_ZERO(srcA + (size_t)(i * 4 + ldrow) * K_DIM +
                               kb * 32 + ldcol);

        // ---- epilogue ----
        const int row0 = t * 16 + g;
        const int row1 = row0 + 8;
#pragma unroll
        for (int j = 0; j < 8; j++) {
            const int col = j * 8 + tig * 2;
            const float b0 = sBias[col], b1 = sBias[col + 1];
            float2 v0 = make_float2(fmaxf(acc[j][0] + b0, 0.f),
                                    fmaxf(acc[j][1] + b1, 0.f));
            float2 v1 = make_float2(fmaxf(acc[j][2] + b0, 0.f),
                                    fmaxf(acc[j][3] + b1, 0.f));
            *reinterpret_cast<float2*>(out + (size_t)row0 * OUT_DIM + col) = v0;
            *reinterpret_cast<float2*>(out + (size_t)row1 * OUT_DIM + col) = v1;
        }
    }
}

// ---------------------------------------------------------------------------
// Launch — two kernels; no memsets (scratch self-cleans each replay).
// ---------------------------------------------------------------------------
extern "C" void kernel_launch(void* const* d_in, const int* in_sizes, int n_in,
                              void* d_out, int out_size) {
    const float* x     = (const float*)d_in[0];
    const int*   edges = (const int*)  d_in[1];
    const float* ew    = (const float*)d_in[2];
    const float* Wl    = (const float*)d_in[3];
    const float* bl    = (const float*)d_in[4];
    const float* Ws    = (const float*)d_in[5];
    const float* bs    = (const float*)d_in[6];
    float*       out   = (float*)d_out;

    scatter_kernel<<<(N_EDGES * 8) / 256, 256>>>(edges, ew, x);

    cudaFuncSetAttribute(gemm_mma_kernel,
                         cudaFuncAttributeMaxDynamicSharedMemorySize,
                         SMEM_TOTAL);
    gemm_mma_kernel<<<148, 512, SMEM_TOTAL>>>(x, Wl, bl, Ws, bs, out);
}